// round 11
// baseline (speedup 1.0000x reference)
#include <cuda_runtime.h>
#include <cstdint>

#define NCTA 128
#define TPB  512
#define HDIM 1024

// Exchange: tagged u64 per GATE SUM = {tag:32 | fp32 pre-activation bits}.
// Word index = gate*1024 + element. Double-buffered by step parity.
__device__ unsigned long long g_gate[2][4 * HDIM];
__device__ float g_xg[4 * HDIM];

// ---------------- PTX helpers ----------------
__device__ __forceinline__ unsigned long long ld_relaxed_u64(const unsigned long long* p) {
    unsigned long long v;
    asm volatile("ld.relaxed.gpu.global.u64 %0, [%1];" : "=l"(v) : "l"(p));
    return v;
}
__device__ __forceinline__ void st_relaxed_u64(unsigned long long* p, unsigned long long v) {
    asm volatile("st.relaxed.gpu.global.u64 [%0], %1;" :: "l"(p), "l"(v) : "memory");
}
__device__ __forceinline__ unsigned long long fma2(unsigned long long a, unsigned long long b,
                                                   unsigned long long c) {
    unsigned long long d;
    asm("fma.rn.f32x2 %0, %1, %2, %3;" : "=l"(d) : "l"(a), "l"(b), "l"(c));
    return d;
}
__device__ __forceinline__ void lds_v2_u64(unsigned addr, unsigned long long& a,
                                           unsigned long long& b) {
    asm volatile("ld.shared.v2.u64 {%0, %1}, [%2];" : "=l"(a), "=l"(b) : "r"(addr));
}
__device__ __forceinline__ float f2sum(unsigned long long v) {
    return __uint_as_float((unsigned)v) + __uint_as_float((unsigned)(v >> 32));
}
__device__ __forceinline__ float sigf(float x) { return 1.0f / (1.0f + __expf(-x)); }
__device__ __forceinline__ float tanh_acc(float x) {
    float e = __expf(2.0f * x);
    return 1.0f - 2.0f / (e + 1.0f);
}

// ---------------- x_gates = x @ W_ih.T + b_ih + b_hh ----------------
__global__ void xgates_kernel(const float* __restrict__ x, const float* __restrict__ Wih,
                              const float* __restrict__ bih, const float* __restrict__ bhh) {
    int lane = threadIdx.x & 31;
    int row  = blockIdx.x * 8 + (threadIdx.x >> 5);
    const float4* wr = (const float4*)(Wih + (size_t)row * HDIM);
    const float4* xr = (const float4*)x;
    float acc = 0.f;
    #pragma unroll
    for (int i = 0; i < 8; i++) {
        float4 w4 = wr[i * 32 + lane];
        float4 x4 = xr[i * 32 + lane];
        acc += w4.x * x4.x + w4.y * x4.y + w4.z * x4.z + w4.w * x4.w;
    }
    #pragma unroll
    for (int off = 16; off; off >>= 1) acc += __shfl_xor_sync(0xffffffffu, acc, off);
    if (lane == 0) g_xg[row] = acc + bih[row] + bhh[row];
}

// ---------------- persistent LSTM rollout (gate-sum broadcast) ----------------
// 128 CTAs x 512 threads (16 warps). Weights exactly as R1: warp w owns global
// gate rows for local rows 2w, 2w+1; 64 weight floats/lane (proven no-spill).
// Per step: each thread polls 8 tagged gate words for elements (tid, tid+512),
// computes activations + locally-replicated c-states, writes h to SMEM (and out
// if this CTA owns the element), bar1, matvec, butterfly, and lane0 publishes
// its 2 fully-reduced gate sums (+xg) IMMEDIATELY -- no bar2, no funnel.
__global__ void __launch_bounds__(TPB, 1)
lstm_kernel(const float* __restrict__ Whh, float* __restrict__ out, int N) {
    __shared__ float h_sm[2][HDIM];   // double buffer, 8KB

    const int tid  = threadIdx.x;
    const int lane = tid & 31;
    const int warp = tid >> 5;
    const int cta  = blockIdx.x;

    // Publisher rows (R1 layout): local rows 2w, 2w+1.
    const int r0l = 2 * warp;
    const int r1l = 2 * warp + 1;
    const int gr0 = (r0l >> 3) * HDIM + cta * 8 + (r0l & 7);
    const int gr1 = (r1l >> 3) * HDIM + cta * 8 + (r1l & 7);
    ulonglong2 w0[8], w1[8];
    #pragma unroll
    for (int j = 0; j < 8; j++) {
        w0[j] = *(const ulonglong2*)(Whh + (size_t)gr0 * HDIM + j * 128 + 4 * lane);
        w1[j] = *(const ulonglong2*)(Whh + (size_t)gr1 * HDIM + j * 128 + 4 * lane);
    }
    const float xgp0 = g_xg[gr0];
    const float xgp1 = g_xg[gr1];

    // Poll-side: elements e0 = tid, e1 = tid + 512 (coalesced across lanes).
    const int e0 = tid, e1 = tid + 512;
    float xq[8];                       // [g*2+k] = g_xg[g*1024 + k*512 + tid]
    #pragma unroll
    for (int g = 0; g < 4; g++) {
        xq[g * 2 + 0] = g_xg[g * HDIM + e0];
        xq[g * 2 + 1] = g_xg[g * HDIM + e1];
    }
    const bool own0 = (e0 >> 3) == cta;
    const bool own1 = (e1 >> 3) == cta;

    const unsigned hbase = (unsigned)__cvta_generic_to_shared(&h_sm[0][0]);

    float c0 = 0.f, c1 = 0.f;          // full c replicated: 2 per thread

    for (int t = 0; t < N; t++) {
        const int buf = t & 1;

        // ---- acquire gate sums for step t ----
        float gs[8];
        if (t == 0) {
            #pragma unroll
            for (int i = 0; i < 8; i++) gs[i] = xq[i];   // h(-1)=0 -> gates = xg
        } else {
            const unsigned long long* bp = g_gate[buf];
            const unsigned tag = (unsigned)t;
            unsigned long long v[8];
            #pragma unroll
            for (int g = 0; g < 4; g++) {               // batch-issue all 8
                v[g * 2 + 0] = ld_relaxed_u64(bp + g * HDIM + e0);
                v[g * 2 + 1] = ld_relaxed_u64(bp + g * HDIM + e1);
            }
            #pragma unroll
            for (int g = 0; g < 4; g++) {               // serial retry loops
                while ((unsigned)(v[g * 2 + 0] >> 32) != tag)
                    v[g * 2 + 0] = ld_relaxed_u64(bp + g * HDIM + e0);
                while ((unsigned)(v[g * 2 + 1] >> 32) != tag)
                    v[g * 2 + 1] = ld_relaxed_u64(bp + g * HDIM + e1);
            }
            #pragma unroll
            for (int i = 0; i < 8; i++) gs[i] = __uint_as_float((unsigned)v[i]);
        }

        // ---- activations + replicated c/h update (2 elements/thread) ----
        float iA = sigf(gs[0]), fA = sigf(gs[2]), gA = tanh_acc(gs[4]), oA = sigf(gs[6]);
        float iB = sigf(gs[1]), fB = sigf(gs[3]), gB = tanh_acc(gs[5]), oB = sigf(gs[7]);
        c0 = fA * c0 + iA * gA;
        c1 = fB * c1 + iB * gB;
        float h0 = oA * tanh_acc(c0);
        float h1 = oB * tanh_acc(c1);
        h_sm[buf][e0] = h0;
        h_sm[buf][e1] = h1;
        if (own0) out[(size_t)t * HDIM + e0] = h0;
        if (own1) out[(size_t)t * HDIM + e1] = h1;
        __syncthreads();   // the only barrier per step

        // ---- matvec: 2 gate rows over full h, packed f32x2 FMAs ----
        const unsigned myb = hbase + (unsigned)(buf * 4096 + lane * 16);
        unsigned long long a0 = 0ull, a1 = 0ull;
        #pragma unroll
        for (int j = 0; j < 8; j++) {
            unsigned long long hA, hB;
            lds_v2_u64(myb + (unsigned)(j * 512), hA, hB);
            a0 = fma2(w0[j].x, hA, a0);  a0 = fma2(w0[j].y, hB, a0);
            a1 = fma2(w1[j].x, hA, a1);  a1 = fma2(w1[j].y, hB, a1);
        }
        float s0 = f2sum(a0), s1 = f2sum(a1);
        #pragma unroll
        for (int off = 16; off; off >>= 1) {
            s0 += __shfl_xor_sync(0xffffffffu, s0, off);
            s1 += __shfl_xor_sync(0xffffffffu, s1, off);
        }

        // ---- publish immediately: no bar2, no funnel ----
        if (lane == 0) {
            const unsigned long long tg = ((unsigned long long)(unsigned)(t + 1)) << 32;
            unsigned long long* gb = g_gate[(t + 1) & 1];
            st_relaxed_u64(gb + gr0, tg | (unsigned long long)__float_as_uint(s0 + xgp0));
            st_relaxed_u64(gb + gr1, tg | (unsigned long long)__float_as_uint(s1 + xgp1));
        }
        // Overwrite safety: publishing tag t+1 over tag t-1 slots is causally
        // ordered (detecting all tag-t implies every CTA passed bar1(t-1), i.e.
        // all t-1 reads done). h_sm[buf] reuse at t+2 is bar1-separated.
        // Replay staleness benign: deterministic identical values.
    }
}

extern "C" void kernel_launch(void* const* d_in, const int* in_sizes, int n_in,
                              void* d_out, int out_size) {
    const float* x   = (const float*)d_in[0];
    const float* Wih = (const float*)d_in[1];
    const float* Whh = (const float*)d_in[2];
    const float* bih = (const float*)d_in[3];
    const float* bhh = (const float*)d_in[4];
    float* out = (float*)d_out;
    const int N = out_size / HDIM;

    xgates_kernel<<<512, 256>>>(x, Wih, bih, bhh);
    lstm_kernel<<<NCTA, TPB>>>(Whh, out, N);
}

// round 13
// speedup vs baseline: 4.7601x; 4.7601x over previous
#include <cuda_runtime.h>
#include <cstdint>

#define NCTA 128
#define TPB  512
#define HDIM 1024

// Exchange: one tagged u64 per h element = {tag:32 | fp32 bits}
__device__ unsigned long long g_hbuf[2][HDIM];
__device__ float g_xg[4 * HDIM];

// ---------------- PTX helpers ----------------
__device__ __forceinline__ unsigned long long ld_relaxed_u64(const unsigned long long* p) {
    unsigned long long v;
    asm volatile("ld.relaxed.gpu.global.u64 %0, [%1];" : "=l"(v) : "l"(p));
    return v;
}
__device__ __forceinline__ void st_relaxed_u64(unsigned long long* p, unsigned long long v) {
    asm volatile("st.relaxed.gpu.global.u64 [%0], %1;" :: "l"(p), "l"(v) : "memory");
}
__device__ __forceinline__ unsigned long long fma2(unsigned long long a, unsigned long long b,
                                                   unsigned long long c) {
    unsigned long long d;
    asm("fma.rn.f32x2 %0, %1, %2, %3;" : "=l"(d) : "l"(a), "l"(b), "l"(c));
    return d;
}
__device__ __forceinline__ void lds_v2_u64(unsigned addr, unsigned long long& a,
                                           unsigned long long& b) {
    asm volatile("ld.shared.v2.u64 {%0, %1}, [%2];" : "=l"(a), "=l"(b) : "r"(addr));
}
__device__ __forceinline__ float f2sum(unsigned long long v) {
    return __uint_as_float((unsigned)v) + __uint_as_float((unsigned)(v >> 32));
}
__device__ __forceinline__ float tanh_acc(float x) {
    float e = __expf(2.0f * x);
    return 1.0f - 2.0f / (e + 1.0f);
}

// ---------------- x_gates = x @ W_ih.T + b_ih + b_hh ----------------
__global__ void xgates_kernel(const float* __restrict__ x, const float* __restrict__ Wih,
                              const float* __restrict__ bih, const float* __restrict__ bhh) {
    int lane = threadIdx.x & 31;
    int row  = blockIdx.x * 8 + (threadIdx.x >> 5);
    const float4* wr = (const float4*)(Wih + (size_t)row * HDIM);
    const float4* xr = (const float4*)x;
    float acc = 0.f;
    #pragma unroll
    for (int i = 0; i < 8; i++) {
        float4 w4 = wr[i * 32 + lane];
        float4 x4 = xr[i * 32 + lane];
        acc += w4.x * x4.x + w4.y * x4.y + w4.z * x4.z + w4.w * x4.w;
    }
    #pragma unroll
    for (int off = 16; off; off >>= 1) acc += __shfl_xor_sync(0xffffffffu, acc, off);
    if (lane == 0) g_xg[row] = acc + bih[row] + bhh[row];
}

// ---------------- persistent LSTM rollout (R1 skeleton, tuned chain) --------
// 128 CTAs x 512 threads (16 warps). CTA owns h elems [8c,8c+8) -> 32 gate
// rows; warp w owns local rows 2w, 2w+1 (64 weight floats/lane, no spill).
// Per step: parallel-issue dual poll -> bar1 -> matvec (f32x2 FMAs) ->
// shfl butterfly -> lane0 stores s+xg to g_sm -> bar2 -> warp0 computes all
// 32 activations in parallel (one expf/lane), 3 shfl gather, lanes<8 update
// c, publish h FIRST, then write out. No spin polls inside the CTA.
__global__ void __launch_bounds__(TPB, 1)
lstm_kernel(const float* __restrict__ Whh, float* __restrict__ out, int N) {
    __shared__ float h_sm[2][HDIM];   // double buffer
    __shared__ float g_sm[32];        // fully-reduced gate sums (+xg)

    const int tid  = threadIdx.x;
    const int lane = tid & 31;
    const int warp = tid >> 5;
    const int cta  = blockIdx.x;

    const int r0l = 2 * warp;
    const int r1l = 2 * warp + 1;
    const int gr0 = (r0l >> 3) * HDIM + cta * 8 + (r0l & 7);
    const int gr1 = (r1l >> 3) * HDIM + cta * 8 + (r1l & 7);

    ulonglong2 w0[8], w1[8];
    #pragma unroll
    for (int j = 0; j < 8; j++) {
        w0[j] = *(const ulonglong2*)(Whh + (size_t)gr0 * HDIM + j * 128 + 4 * lane);
        w1[j] = *(const ulonglong2*)(Whh + (size_t)gr1 * HDIM + j * 128 + 4 * lane);
    }
    const float xg0 = g_xg[gr0];
    const float xg1 = g_xg[gr1];

    const unsigned hbase = (unsigned)__cvta_generic_to_shared(&h_sm[0][0]);
    // Epilogue activation form: gate = lane>>3; gate 2 -> tanh, else sigmoid.
    const float gam = ((lane >> 3) == 2) ? 2.f : -1.f;

    float c_state = 0.f;   // live in warp0 lanes 0..7

    for (int t = 0; t < N; t++) {
        const int buf = t & 1;

        // ---- acquire h(t): both tagged loads issued up front, serial retries ----
        if (t == 0) {
            *(float2*)&h_sm[0][2 * tid] = make_float2(0.f, 0.f);
        } else {
            const unsigned long long* bp = g_hbuf[buf] + 2 * tid;
            const unsigned tag = (unsigned)t;
            unsigned long long v0 = ld_relaxed_u64(bp + 0);
            unsigned long long v1 = ld_relaxed_u64(bp + 1);
            while ((unsigned)(v0 >> 32) != tag) v0 = ld_relaxed_u64(bp + 0);
            while ((unsigned)(v1 >> 32) != tag) v1 = ld_relaxed_u64(bp + 1);
            *(float2*)&h_sm[buf][2 * tid] =
                make_float2(__uint_as_float((unsigned)v0), __uint_as_float((unsigned)v1));
        }
        __syncthreads();   // bar1

        // ---- matvec: 2 gate rows, packed f32x2 FMAs ----
        const unsigned myb = hbase + (unsigned)(buf * 4096 + lane * 16);
        unsigned long long a0 = 0ull, a1 = 0ull;
        #pragma unroll
        for (int j = 0; j < 8; j++) {
            unsigned long long hA, hB;
            lds_v2_u64(myb + (unsigned)(j * 512), hA, hB);
            a0 = fma2(w0[j].x, hA, a0);  a0 = fma2(w0[j].y, hB, a0);
            a1 = fma2(w1[j].x, hA, a1);  a1 = fma2(w1[j].y, hB, a1);
        }
        float s0 = f2sum(a0), s1 = f2sum(a1);
        #pragma unroll
        for (int off = 16; off; off >>= 1) {
            s0 += __shfl_xor_sync(0xffffffffu, s0, off);
            s1 += __shfl_xor_sync(0xffffffffu, s1, off);
        }
        if (lane == 0) {
            g_sm[r0l] = s0 + xg0;
            g_sm[r1l] = s1 + xg1;
        }
        __syncthreads();   // bar2

        // ---- epilogue: warp0, 32 parallel activations, 8 parallel c/h ----
        if (warp == 0) {
            float s = g_sm[lane];
            float e = __expf(gam * s);
            float r = 1.0f / (1.0f + e);
            float a = ((lane >> 3) == 2) ? fmaf(-2.f, r, 1.f) : r;  // tanh vs sig

            const int el = lane & 7;
            float f_ = __shfl_sync(0xffffffffu, a, el + 8);
            float g_ = __shfl_sync(0xffffffffu, a, el + 16);
            float o_ = __shfl_sync(0xffffffffu, a, el + 24);

            if (lane < 8) {
                c_state = f_ * c_state + a * g_;        // a == i_ for lanes<8
                float hv = o_ * tanh_acc(c_state);
                unsigned long long pv =
                    ((unsigned long long)(unsigned)(t + 1) << 32) |
                    (unsigned long long)__float_as_uint(hv);
                st_relaxed_u64(&g_hbuf[(t + 1) & 1][cta * 8 + lane], pv);  // publish first
                out[(size_t)t * HDIM + cta * 8 + lane] = hv;
            }
        }
        // h_sm[buf] reuse at t+2: ordered by publish->poll causal chain.
        // g_sm reuse at t+1: ordered by bar1(t+1) between epilogue read and store.
    }
}

extern "C" void kernel_launch(void* const* d_in, const int* in_sizes, int n_in,
                              void* d_out, int out_size) {
    const float* x   = (const float*)d_in[0];
    const float* Wih = (const float*)d_in[1];
    const float* Whh = (const float*)d_in[2];
    const float* bih = (const float*)d_in[3];
    const float* bhh = (const float*)d_in[4];
    float* out = (float*)d_out;
    const int N = out_size / HDIM;

    xgates_kernel<<<512, 256>>>(x, Wih, bih, bhh);
    lstm_kernel<<<NCTA, TPB>>>(Whh, out, N);
}